// round 17
// baseline (speedup 1.0000x reference)
#include <cuda_runtime.h>
#include <cstdint>

#define CD 512
#define KD 65536
#define BM 128
#define BK 64
#define NPAIRS 10                    // 4x4 lower-triangle tile pairs
#define SPLITS 29
#define NCHUNK (KD / BK)             // 1024
#define NSTAGE 3
#define WSTRIDE 36                   // 32-bit words per smem row (conflict-free: bank=4g+t+c)
#define TILE_W (BM * WSTRIDE)        // 4608 words per tile
#define STAGE_W (2 * TILE_W)
#define SMEM_BYTES (NSTAGE * STAGE_W * 4)   // 110592 -> 2 CTAs/SM

// Deterministic split-K planes + bf16 copy of X (no device allocation allowed)
__device__ float g_part[(size_t)NPAIRS * SPLITS * 16384];
__device__ uint32_t g_xw[(size_t)CD * KD / 2];      // X as bf16 pairs (64 MB)

__device__ __forceinline__ uint32_t s2u(const void* p) {
    uint32_t a;
    asm("{ .reg .u64 t; cvta.to.shared.u64 t, %1; cvt.u32.u64 %0, t; }" : "=r"(a) : "l"(p));
    return a;
}

// pack (lo=x, hi=y) into bf16x2 with round-to-nearest (unbiased)
__device__ __forceinline__ uint32_t bf2(float x, float y) {
    uint32_t r;
    asm("cvt.rn.bf16x2.f32 %0, %1, %2;" : "=r"(r) : "f"(y), "f"(x));
    return r;
}

__device__ __forceinline__ void cp16(uint32_t dst, const void* src) {
    asm volatile("cp.async.cg.shared.global [%0], [%1], 16;" :: "r"(dst), "l"(src) : "memory");
}

// ---- pre-convert: fp32 X -> bf16 pairs (memory-bound) ----
__global__ void to_bf16(const float* __restrict__ X) {
    const size_t i = (size_t)blockIdx.x * blockDim.x + threadIdx.x;   // 0 .. CD*KD/8-1
    const float4* p = (const float4*)X + 2 * i;
    float4 a = p[0], b = p[1];
    uint4 w;
    w.x = bf2(a.x, a.y); w.y = bf2(a.z, a.w);
    w.z = bf2(b.x, b.y); w.w = bf2(b.z, b.w);
    ((uint4*)g_xw)[i] = w;
}

__global__ __launch_bounds__(128, 2) void gram_mma() {
    extern __shared__ uint32_t smw[];
    const uint32_t sb = s2u(smw);

    const int pair  = blockIdx.x % NPAIRS;
    const int split = blockIdx.x / NPAIRS;

    int bi = 0;
    while ((bi + 1) * (bi + 2) / 2 <= pair) bi++;
    const int bj = pair - bi * (bi + 1) / 2;
    const bool diag = (bi == bj);

    const int c0 = (split * NCHUNK) / SPLITS;
    const int c1 = ((split + 1) * NCHUNK) / SPLITS;

    const int tid  = threadIdx.x;
    const int lane = tid & 31;
    const int wid  = tid >> 5;
    const int wr   = wid >> 1;          // 0..1 -> rows 64*wr
    const int wc   = wid & 1;           // 0..1 -> cols 64*wc
    const int g    = lane >> 2;         // 0..7
    const int t    = lane & 3;          // 0..3

    // loader: bf16 rows; per tile 128 rows x 8 granules(16B=8k); 8 cp16/thread/tile
    const int ldr = tid >> 3;           // 0..15 (+16*r8)
    const int g16 = tid & 7;            // 16B granule (8 k-values)
    const char* gA = (const char*)g_xw + ((size_t)(bi * BM + ldr) * KD + g16 * 8) * 2;
    const char* gB = (const char*)g_xw + ((size_t)(bj * BM + ldr) * KD + g16 * 8) * 2;

    float acc[4][8][4];
    #pragma unroll
    for (int mi = 0; mi < 4; mi++)
        #pragma unroll
        for (int ni = 0; ni < 8; ni++)
            #pragma unroll
            for (int e = 0; e < 4; e++) acc[mi][ni][e] = 0.f;

    const int niters = c1 - c0;

    // ---- prologue ----
    #pragma unroll
    for (int s = 0; s < NSTAGE - 1; s++) {
        if (s < niters) {
            const int c = c0 + s;
            const uint32_t base = sb + (uint32_t)(s * STAGE_W) * 4u;
            #pragma unroll
            for (int r8 = 0; r8 < 8; r8++) {
                const uint32_t woff = (uint32_t)((ldr + 16 * r8) * WSTRIDE + 4 * g16) * 4u;
                cp16(base + woff, gA + ((size_t)(16 * r8) * KD + (size_t)c * BK) * 2);
                if (!diag)
                    cp16(base + (uint32_t)(TILE_W * 4) + woff,
                         gB + ((size_t)(16 * r8) * KD + (size_t)c * BK) * 2);
            }
        }
        asm volatile("cp.async.commit_group;" ::: "memory");
    }

    for (int i = 0; i < niters; i++) {
        asm volatile("cp.async.wait_group %0;" :: "n"(NSTAGE - 2) : "memory");
        __syncthreads();

        {
            const int cn = c0 + i + NSTAGE - 1;
            if (cn < c1) {
                const int st = (i + NSTAGE - 1) % NSTAGE;
                const uint32_t base = sb + (uint32_t)(st * STAGE_W) * 4u;
                #pragma unroll
                for (int r8 = 0; r8 < 8; r8++) {
                    const uint32_t woff = (uint32_t)((ldr + 16 * r8) * WSTRIDE + 4 * g16) * 4u;
                    cp16(base + woff, gA + ((size_t)(16 * r8) * KD + (size_t)cn * BK) * 2);
                    if (!diag)
                        cp16(base + (uint32_t)(TILE_W * 4) + woff,
                             gB + ((size_t)(16 * r8) * KD + (size_t)cn * BK) * 2);
                }
            }
            asm volatile("cp.async.commit_group;" ::: "memory");
        }

        // compute: 4 k-steps of K=16 bf16 mma; frags are direct word loads (conflict-free)
        const uint32_t* As = smw + (i % NSTAGE) * STAGE_W;
        const uint32_t* Bs = diag ? As : (As + TILE_W);

        #pragma unroll
        for (int kk = 0; kk < 4; kk++) {
            const int kw = kk * 8 + t;      // word index of k-pair within row
            uint32_t ar[4][4];
            #pragma unroll
            for (int mi = 0; mi < 4; mi++) {
                const int r = 64 * wr + 16 * mi + g;
                ar[mi][0] = As[r * WSTRIDE + kw];
                ar[mi][1] = As[(r + 8) * WSTRIDE + kw];
                ar[mi][2] = As[r * WSTRIDE + kw + 4];
                ar[mi][3] = As[(r + 8) * WSTRIDE + kw + 4];
            }
            uint32_t br[8][2];
            #pragma unroll
            for (int ni = 0; ni < 8; ni++) {
                const int n = 64 * wc + 8 * ni + g;
                br[ni][0] = Bs[n * WSTRIDE + kw];
                br[ni][1] = Bs[n * WSTRIDE + kw + 4];
            }
            #pragma unroll
            for (int mi = 0; mi < 4; mi++)
                #pragma unroll
                for (int ni = 0; ni < 8; ni++) {
                    asm volatile(
                        "mma.sync.aligned.m16n8k16.row.col.f32.bf16.bf16.f32 "
                        "{%0,%1,%2,%3}, {%4,%5,%6,%7}, {%8,%9}, {%0,%1,%2,%3};"
                        : "+f"(acc[mi][ni][0]), "+f"(acc[mi][ni][1]),
                          "+f"(acc[mi][ni][2]), "+f"(acc[mi][ni][3])
                        : "r"(ar[mi][0]), "r"(ar[mi][1]), "r"(ar[mi][2]), "r"(ar[mi][3]),
                          "r"(br[ni][0]), "r"(br[ni][1]));
                }
        }
    }

    // epilogue: partial 128x128 tile -> contiguous plane (pair*SPLITS + split)
    float* pl = g_part + (size_t)(pair * SPLITS + split) * 16384;
    #pragma unroll
    for (int mi = 0; mi < 4; mi++) {
        const int r = 64 * wr + 16 * mi + g;
        #pragma unroll
        for (int ni = 0; ni < 8; ni++) {
            const int c = 64 * wc + 8 * ni + 2 * t;
            *(float2*)(pl + r * 128 + c)       = make_float2(acc[mi][ni][0], acc[mi][ni][1]);
            *(float2*)(pl + (r + 8) * 128 + c) = make_float2(acc[mi][ni][2], acc[mi][ni][3]);
        }
    }
}

// Sum 29 contiguous planes per pair; one float per thread; mirror to upper triangle.
__global__ void gram_reduce(float* __restrict__ out) {
    const int idx  = blockIdx.x * blockDim.x + threadIdx.x;   // 0..163839
    const int pair = idx >> 14;
    const int e    = idx & 16383;

    int bi = 0;
    while ((bi + 1) * (bi + 2) / 2 <= pair) bi++;
    const int bj = pair - bi * (bi + 1) / 2;

    const float* base = g_part + (size_t)pair * SPLITS * 16384 + e;
    float s = 0.f;
    #pragma unroll
    for (int k = 0; k < SPLITS; k++)
        s += base[k * 16384];

    const int r = e >> 7, c = e & 127;
    const int gi = bi * BM + r, gj = bj * BM + c;
    out[(size_t)gi * CD + gj] = s;
    out[(size_t)gj * CD + gi] = s;
}

extern "C" void kernel_launch(void* const* d_in, const int* in_sizes, int n_in,
                              void* d_out, int out_size) {
    const float* x = (const float*)d_in[0];   // [1,512,256,256] = [512, 65536]
    float* out = (float*)d_out;               // [1,1,512,512]

    to_bf16<<<(int)((size_t)CD * KD / 8 / 256), 256>>>(x);
    cudaFuncSetAttribute(gram_mma, cudaFuncAttributeMaxDynamicSharedMemorySize, SMEM_BYTES);
    gram_mma<<<NPAIRS * SPLITS, 128, SMEM_BYTES>>>();
    gram_reduce<<<NPAIRS * 64, 256>>>(out);
}